// round 9
// baseline (speedup 1.0000x reference)
#include <cuda_runtime.h>
#include <cuda_bf16.h>
#include <math.h>
#include <stdint.h>

#define N_NODES 50000
#define E_EDGES 800000
#define N_ET    (E_EDGES + N_NODES)   // 850000 edges incl. self loops
#define EDIM    101
#define LP      104                   // padded loop_attr pitch
#define HC      128
#define NH      4

// ---- mma edge tile config ----
#define TILE_E  128
#define NTILES  ((N_ET + TILE_E - 1) / TILE_E)
#define NKS     7                     // 7 k-steps of 16 (K padded to 112)
#define PW      60                    // row pitch in bf16x2 words (120 bf16)

// smem byte offsets (no ee buffer anymore)
#define SM_SS    0
#define SM_DS    512
#define SM_AHI   1024                      // 128*60*4 = 30720
#define SM_ALO   (SM_AHI + 128*PW*4)
#define SM_BHI   (SM_ALO + 128*PW*4)
#define SM_BLO   (SM_BHI + 128*PW*4)
#define SM_TOTAL (SM_BLO + 128*PW*4)       // 123904 bytes

// ------------------------------ scratch ------------------------------------
__device__ int   g_is64;
__device__ int   g_eidx[2 * E_EDGES];
__device__ float g_loop[(size_t)N_NODES * LP];
__device__ float g_cnt [N_NODES];
__device__ float g_xl  [(size_t)N_NODES * HC];
__device__ float g_xr  [(size_t)N_NODES * HC];
__device__ float g_h   [(size_t)N_NODES * HC];
__device__ float g_t1  [(size_t)N_NODES * HC];
__device__ float g_den [(size_t)N_NODES * NH];
__device__ float g_agg [(size_t)N_NODES * HC];

// ------------------------------ helpers ------------------------------------
__device__ __forceinline__ void redAdd4(float* p, float4 v) {
    asm volatile("red.global.add.v4.f32 [%0], {%1,%2,%3,%4};"
                 :: "l"(p), "f"(v.x), "f"(v.y), "f"(v.z), "f"(v.w) : "memory");
}
__device__ __forceinline__ void redAdd2(float* p, float2 v) {
    asm volatile("red.global.add.v2.f32 [%0], {%1,%2};"
                 :: "l"(p), "f"(v.x), "f"(v.y) : "memory");
}

// packed fp32x2 (node GEMMs; exact math)
__device__ __forceinline__ void fma2(unsigned long long& d,
                                     unsigned long long a, unsigned long long b) {
    asm("fma.rn.f32x2 %0, %1, %2, %0;" : "+l"(d) : "l"(a), "l"(b));
}
__device__ __forceinline__ unsigned long long dup2(float x) {
    unsigned long long r;
    asm("mov.b64 %0, {%1, %1};" : "=l"(r) : "r"(__float_as_uint(x)));
    return r;
}
__device__ __forceinline__ float2 unpk2(unsigned long long v) {
    unsigned int lo, hi;
    asm("mov.b64 {%0, %1}, %2;" : "=r"(lo), "=r"(hi) : "l"(v));
    return make_float2(__uint_as_float(lo), __uint_as_float(hi));
}

// truncation-based bf16 hi/lo split of a float pair (PRMT pack; residual 2^-16)
__device__ __forceinline__ void split_trunc(float v0, float v1,
                                            uint32_t& hi, uint32_t& lo) {
    uint32_t u0 = __float_as_uint(v0), u1 = __float_as_uint(v1);
    hi = __byte_perm(u0, u1, 0x7632);
    float r0 = v0 - __uint_as_float(u0 & 0xFFFF0000u);
    float r1 = v1 - __uint_as_float(u1 & 0xFFFF0000u);
    lo = __byte_perm(__float_as_uint(r0), __float_as_uint(r1), 0x7632);
}

// HMMA m16n8k16 bf16 (baseline PTX, sm_80+)
__device__ __forceinline__ void mma_bf16(float* d,
                                         uint32_t a0, uint32_t a1, uint32_t a2, uint32_t a3,
                                         uint32_t b0, uint32_t b1) {
    asm volatile("mma.sync.aligned.m16n8k16.row.col.f32.bf16.bf16.f32 "
                 "{%0,%1,%2,%3}, {%4,%5,%6,%7}, {%8,%9}, {%0,%1,%2,%3};"
                 : "+f"(d[0]), "+f"(d[1]), "+f"(d[2]), "+f"(d[3])
                 : "r"(a0), "r"(a1), "r"(a2), "r"(a3), "r"(b0), "r"(b1));
}

// ------------------------------ index dtype hedge ---------------------------
__global__ void detect_idx(const void* ei) {
    const int* p = (const int*)ei;
    int all0 = 1;
    for (int i = 1; i < 64; i += 2) if (p[i] != 0) all0 = 0;
    g_is64 = all0;
}

__global__ void conv_idx(const void* ei) {
    int i = blockIdx.x * blockDim.x + threadIdx.x;
    if (i >= 2 * E_EDGES) return;
    int v;
    if (g_is64) v = (int)((const long long*)ei)[i];
    else        v = ((const int*)ei)[i];
    g_eidx[i] = v;
}

// ------------------------------ self-loop attr -----------------------------
__global__ void pre_init() {
    size_t i = (size_t)blockIdx.x * blockDim.x + threadIdx.x;
    if (i < (size_t)N_NODES * LP) g_loop[i] = 0.f;
    if (i < N_NODES) g_cnt[i] = 0.f;
}

__global__ void loop_accum(const int* __restrict__ dst, const float* __restrict__ ea) {
    int e = blockIdx.x * blockDim.x + threadIdx.x;
    if (e >= E_EDGES) return;
    int d = dst[e];
    float* out = g_loop + (size_t)d * LP;
    const float* a = ea + (size_t)e * EDIM;
#pragma unroll
    for (int k = 0; k < 100; k += 4) {
        float4 v = make_float4(a[k], a[k+1], a[k+2], a[k+3]);
        redAdd4(out + k, v);
    }
    atomicAdd(out + 100, a[100]);
    atomicAdd(&g_cnt[d], 1.0f);
}

__global__ void loop_fin() {
    size_t i = (size_t)blockIdx.x * blockDim.x + threadIdx.x;
    if (i >= (size_t)N_NODES * EDIM) return;
    int n = (int)(i / EDIM);
    int k = (int)(i - (size_t)n * EDIM);
    g_loop[(size_t)n * LP + k] *= 1.f / fmaxf(g_cnt[n], 1.f);
}

// ------------------------------ SGEMM (M x 128 = A[M,128] @ B[128,128]) ----
__global__ void sgemm128x128(const float* __restrict__ A, const float* __restrict__ B,
                             const float* __restrict__ bias, float* __restrict__ C,
                             int M, int relu) {
    __shared__ float As[8 * 132];
    __shared__ float Bs[8 * 128];
    int t = threadIdx.x;
    int m0 = blockIdx.x << 7;
    int la_m = t >> 1, la_k = (t & 1) << 2;
    int lb_k = t >> 5, lb_n = (t & 31) << 2;
    int tm = (t >> 4) << 3;
    int tn = (t & 15) << 2;

    unsigned long long acc[8][4];
#pragma unroll
    for (int i = 0; i < 8; i++)
#pragma unroll
        for (int j = 0; j < 4; j++) acc[i][j] = 0ull;

    for (int k0 = 0; k0 < 128; k0 += 8) {
        float4 av = make_float4(0.f, 0.f, 0.f, 0.f);
        if (m0 + la_m < M)
            av = *(const float4*)(A + (size_t)(m0 + la_m) * 128 + k0 + la_k);
        As[(la_k + 0) * 132 + la_m] = av.x;
        As[(la_k + 1) * 132 + la_m] = av.y;
        As[(la_k + 2) * 132 + la_m] = av.z;
        As[(la_k + 3) * 132 + la_m] = av.w;
        *(float4*)(Bs + lb_k * 128 + lb_n) =
            *(const float4*)(B + (size_t)(k0 + lb_k) * 128 + lb_n);
        __syncthreads();
#pragma unroll
        for (int k = 0; k < 8; k++) {
            float a[8];
            *(float4*)(a)     = *(const float4*)(As + k * 132 + tm);
            *(float4*)(a + 4) = *(const float4*)(As + k * 132 + tm + 4);
            ulonglong2 bA = *(const ulonglong2*)(Bs + k * 128 + tn);
            ulonglong2 bB = *(const ulonglong2*)(Bs + k * 128 + tn + 64);
            unsigned long long bp[4] = {bA.x, bA.y, bB.x, bB.y};
#pragma unroll
            for (int i = 0; i < 8; i++) {
                unsigned long long ad = dup2(a[i]);
#pragma unroll
                for (int j = 0; j < 4; j++) fma2(acc[i][j], ad, bp[j]);
            }
        }
        __syncthreads();
    }
#pragma unroll
    for (int i = 0; i < 8; i++) {
        int m = m0 + tm + i;
        if (m >= M) break;
        float o0[4], o1[4];
        float2 p0 = unpk2(acc[i][0]), p1 = unpk2(acc[i][1]);
        float2 p2 = unpk2(acc[i][2]), p3 = unpk2(acc[i][3]);
        o0[0] = p0.x + bias[tn + 0];  o0[1] = p0.y + bias[tn + 1];
        o0[2] = p1.x + bias[tn + 2];  o0[3] = p1.y + bias[tn + 3];
        o1[0] = p2.x + bias[tn + 64]; o1[1] = p2.y + bias[tn + 65];
        o1[2] = p3.x + bias[tn + 66]; o1[3] = p3.y + bias[tn + 67];
        if (relu) {
#pragma unroll
            for (int j = 0; j < 4; j++) {
                o0[j] = fmaxf(o0[j], 0.f);
                o1[j] = fmaxf(o1[j], 0.f);
            }
        }
        *(float4*)(C + (size_t)m * 128 + tn)      = *(float4*)(o0);
        *(float4*)(C + (size_t)m * 128 + tn + 64) = *(float4*)(o1);
    }
}

// ------------------------------ per-layer init ------------------------------
__global__ void layer_init() {
    size_t i = (size_t)blockIdx.x * blockDim.x + threadIdx.x;
    if (i < (size_t)N_NODES * HC) g_agg[i] = 0.f;
    if (i < (size_t)N_NODES * NH) g_den[i] = 0.f;
}

// ==== HMMA fused edge kernel: pipelined staging + bf16 hi/lo 3-term GEMM +
//      fragment-direct epilogue (per-warp logit/exp/aggregate, no ee buffer) ==
__device__ __forceinline__ void prefetch_attrs(size_t e, int kbase, float* pf,
                                               const float* __restrict__ eattr) {
    bool ok = (e < (size_t)N_ET);
    const float* bp = (e < E_EDGES) ? (eattr + e * EDIM)
                    : (g_loop + (ok ? (e - E_EDGES) : 0) * (size_t)LP);
#pragma unroll
    for (int i = 0; i < 28; i++) {
        int k = kbase + i;
        pf[i] = (ok && k < EDIM) ? bp[k] : 0.f;
    }
}

__global__ __launch_bounds__(512, 1)
void edge_mma(const int* __restrict__ src, const int* __restrict__ dst,
              const float* __restrict__ eattr,
              const float* __restrict__ We, const float* __restrict__ att) {
    extern __shared__ __align__(16) char sm[];
    int*      ssS  = (int*)(sm + SM_SS);
    int*      dsS  = (int*)(sm + SM_DS);
    uint32_t* Ahi  = (uint32_t*)(sm + SM_AHI);
    uint32_t* Alo  = (uint32_t*)(sm + SM_ALO);
    uint32_t* Bhi  = (uint32_t*)(sm + SM_BHI);
    uint32_t* Blo  = (uint32_t*)(sm + SM_BLO);

    int t = threadIdx.x;
    int lane = t & 31;
    int w = t >> 5;                 // 0..15
    int mb = w >> 1;                // edge block (16 edges)
    int half = w & 1;               // channel half (64 ch = heads 2*half, 2*half+1)
    int r0 = lane >> 2;             // fragment row
    int kp = lane & 3;              // fragment col-pair

    // ---- stage B = We (k-major per channel row) hi/lo, once ----
    for (int i = t; i < 128 * 56; i += 512) {
        int c = i / 56, kq = i % 56;
        int k = kq * 2;
        float v0 = (k     < EDIM) ? We[(size_t)k * 128 + c]       : 0.f;
        float v1 = (k + 1 < EDIM) ? We[(size_t)(k + 1) * 128 + c] : 0.f;
        uint32_t h, l;
        split_trunc(v0, v1, h, l);
        Bhi[c * PW + kq] = h;
        Blo[c * PW + kq] = l;
    }

    // per-thread att fragment (channels cb + 8*nb + {0,1})
    int cb = (half << 6) + (kp << 1);
    int h0 = half << 1;
    float2 attv[8];
#pragma unroll
    for (int nb = 0; nb < 8; nb++)
        attv[nb] = *(const float2*)(att + cb + (nb << 3));

    int e_st = t >> 2;              // staging: edge slot (0..127)
    int kq0  = (t & 3) * 14;        // staging: word range start
    int kbase = kq0 * 2;

    // prefetch first tile's attrs into registers
    float pf[28];
    prefetch_attrs((size_t)blockIdx.x * TILE_E + e_st, kbase, pf, eattr);

    for (int tile = blockIdx.x; tile < NTILES; tile += gridDim.x) {
        size_t e0 = (size_t)tile * TILE_E;
        __syncthreads();            // prev tile reads of A/ss complete

        if (t < TILE_E) {
            size_t e = e0 + t;
            int s = 0, d = 0;
            if (e < (size_t)N_ET) {
                if (e < E_EDGES) { s = src[e]; d = dst[e]; }
                else             { s = d = (int)(e - E_EDGES); }
            }
            ssS[t] = s; dsS[t] = d;
        }

        // convert prefetched A attrs -> hi/lo smem
        {
            uint32_t* ah = Ahi + e_st * PW;
            uint32_t* al = Alo + e_st * PW;
#pragma unroll
            for (int i = 0; i < 14; i++) {
                uint32_t h, l;
                split_trunc(pf[2*i], pf[2*i + 1], h, l);
                ah[kq0 + i] = h;
                al[kq0 + i] = l;
            }
        }
        // issue next tile's prefetch (lands during MMA/epilogue)
        {
            int ntile = tile + gridDim.x;
            if (ntile < NTILES)
                prefetch_attrs((size_t)ntile * TILE_E + e_st, kbase, pf, eattr);
        }
        __syncthreads();

        // ---- HMMA: D = Ahi*Bhi + Ahi*Blo + Alo*Bhi ----
        float acc[8][4];
#pragma unroll
        for (int nb = 0; nb < 8; nb++)
#pragma unroll
            for (int j = 0; j < 4; j++) acc[nb][j] = 0.f;

        const uint32_t* Aw_h = Ahi + (mb << 4) * PW;
        const uint32_t* Aw_l = Alo + (mb << 4) * PW;
        const uint32_t* Bw_h = Bhi + (half << 6) * PW;
        const uint32_t* Bw_l = Blo + (half << 6) * PW;

#pragma unroll
        for (int ks = 0; ks < NKS; ks++) {
            int abase = r0 * PW + ks * 8 + kp;
            uint32_t ah0 = Aw_h[abase],     ah1 = Aw_h[abase + 8 * PW];
            uint32_t ah2 = Aw_h[abase + 4], ah3 = Aw_h[abase + 8 * PW + 4];
            uint32_t al0 = Aw_l[abase],     al1 = Aw_l[abase + 8 * PW];
            uint32_t al2 = Aw_l[abase + 4], al3 = Aw_l[abase + 8 * PW + 4];
#pragma unroll
            for (int nb = 0; nb < 8; nb++) {
                int bbase = ((nb << 3) + r0) * PW + ks * 8 + kp;
                uint32_t bh0 = Bw_h[bbase], bh1 = Bw_h[bbase + 4];
                uint32_t bl0 = Bw_l[bbase], bl1 = Bw_l[bbase + 4];
                mma_bf16(acc[nb], ah0, ah1, ah2, ah3, bh0, bh1);
                mma_bf16(acc[nb], ah0, ah1, ah2, ah3, bl0, bl1);
                mma_bf16(acc[nb], al0, al1, al2, al3, bh0, bh1);
            }
        }

        // ---- fragment-direct epilogue (per warp: 16 edges x 2 heads) ----
        // thread owns edges el0 = 16*mb + r0 and el1 = el0 + 8,
        // channels cb + 8*nb + {0,1}. All lanes run shuffles unconditionally.
        int el0 = (mb << 4) + r0;
        int el1 = el0 + 8;
        bool v0 = (e0 + el0 < (size_t)N_ET);
        bool v1 = (e0 + el1 < (size_t)N_ET);
        int s0 = ssS[el0], d0 = dsS[el0];
        int s1 = ssS[el1], d1 = dsS[el1];

#pragma unroll
        for (int row = 0; row < 2; row++) {
            int s = row ? s1 : s0;
            int d = row ? d1 : d0;
            bool valid = row ? v1 : v0;
            const float* xlp = g_xl + (size_t)s * HC + cb;
            const float* xrp = g_xr + (size_t)d * HC + cb;
            float2 xlv[8], xrv[8];
#pragma unroll
            for (int nb = 0; nb < 8; nb++) {
                xlv[nb] = *(const float2*)(xlp + (nb << 3));
                xrv[nb] = *(const float2*)(xrp + (nb << 3));
            }
            float lgA = 0.f, lgB = 0.f;
#pragma unroll
            for (int nb = 0; nb < 8; nb++) {
                float zx = acc[nb][2*row]     + xlv[nb].x + xrv[nb].x;
                float zy = acc[nb][2*row + 1] + xlv[nb].y + xrv[nb].y;
                zx = (zx > 0.f) ? zx : 0.2f * zx;
                zy = (zy > 0.f) ? zy : 0.2f * zy;
                float p = zx * attv[nb].x + zy * attv[nb].y;
                if (nb < 4) lgA += p; else lgB += p;
            }
            lgA += __shfl_xor_sync(0xffffffffu, lgA, 1);
            lgA += __shfl_xor_sync(0xffffffffu, lgA, 2);
            lgB += __shfl_xor_sync(0xffffffffu, lgB, 1);
            lgB += __shfl_xor_sync(0xffffffffu, lgB, 2);
            float exA = __expf(lgA), exB = __expf(lgB);
            if (valid) {
                if (kp == 0) atomicAdd(&g_den[(size_t)d * NH + h0],     exA);
                if (kp == 1) atomicAdd(&g_den[(size_t)d * NH + h0 + 1], exB);
                float* ap = g_agg + (size_t)d * HC + cb;
#pragma unroll
                for (int nb = 0; nb < 8; nb++) {
                    float ex = (nb < 4) ? exA : exB;
                    redAdd2(ap + (nb << 3),
                            make_float2(ex * xlv[nb].x, ex * xlv[nb].y));
                }
            }
        }
    }
}

// --------------------- h = relu(agg/(den+eps) + bias) ----------------------
__global__ void node_finalize(const float* __restrict__ bias, float* __restrict__ out) {
    size_t i = (size_t)blockIdx.x * blockDim.x + threadIdx.x;
    if (i >= (size_t)N_NODES * HC) return;
    int n = (int)(i >> 7), c = (int)(i & 127);
    float den = g_den[(size_t)n * NH + (c >> 5)];
    float v = g_agg[i] / (den + 1e-16f) + bias[c];
    out[i] = fmaxf(v, 0.f);
}

// --------------------- MLP tail: relu(t1@W2+b2) @ W3 + b3 ------------------
__global__ void mlp_tail(const float* __restrict__ W2, const float* __restrict__ b2,
                         const float* __restrict__ W3, const float* __restrict__ b3,
                         float* __restrict__ out) {
    __shared__ float W2s[128 * 64];
    __shared__ float t1s[16 * 132];
    __shared__ float W3s[64];
    int t = threadIdx.x;
    int n0 = blockIdx.x * 16;
    for (int i = t; i < 128 * 64 / 4; i += 128)
        ((float4*)W2s)[i] = ((const float4*)W2)[i];
    if (t < 64) W3s[t] = W3[t];
    for (int i = t; i < 16 * 128; i += 128) {
        int ln = i >> 7, k = i & 127;
        int n = n0 + ln;
        t1s[ln * 132 + k] = (n < N_NODES) ? g_t1[(size_t)n * 128 + k] : 0.f;
    }
    __syncthreads();
    int ln = t >> 3, jg = t & 7;
    float acc[8] = {0.f, 0.f, 0.f, 0.f, 0.f, 0.f, 0.f, 0.f};
#pragma unroll 4
    for (int k = 0; k < 128; k++) {
        float a = t1s[ln * 132 + k];
        float4 w0 = *(const float4*)(W2s + k * 64 + jg * 8);
        float4 w1 = *(const float4*)(W2s + k * 64 + jg * 8 + 4);
        acc[0] += a * w0.x; acc[1] += a * w0.y; acc[2] += a * w0.z; acc[3] += a * w0.w;
        acc[4] += a * w1.x; acc[5] += a * w1.y; acc[6] += a * w1.z; acc[7] += a * w1.w;
    }
    float part = 0.f;
#pragma unroll
    for (int j = 0; j < 8; j++) {
        float t2 = fmaxf(acc[j] + b2[jg * 8 + j], 0.f);
        part += t2 * W3s[jg * 8 + j];
    }
    part += __shfl_down_sync(0xffffffffu, part, 4, 8);
    part += __shfl_down_sync(0xffffffffu, part, 2, 8);
    part += __shfl_down_sync(0xffffffffu, part, 1, 8);
    int n = n0 + ln;
    if (jg == 0 && n < N_NODES) out[n] = part + b3[0];
}

// ------------------------------ launch -------------------------------------
extern "C" void kernel_launch(void* const* d_in, const int* in_sizes, int n_in,
                              void* d_out, int out_size) {
    const float* x       = (const float*)d_in[0];
    const void*  ei_raw  = d_in[1];
    const float* ea      = (const float*)d_in[2];
    const float* c1_Wl   = (const float*)d_in[3];
    const float* c1_bl   = (const float*)d_in[4];
    const float* c1_Wr   = (const float*)d_in[5];
    const float* c1_br   = (const float*)d_in[6];
    const float* c1_We   = (const float*)d_in[7];
    const float* c1_att  = (const float*)d_in[8];
    const float* c1_bias = (const float*)d_in[9];
    const float* c2_Wl   = (const float*)d_in[10];
    const float* c2_bl   = (const float*)d_in[11];
    const float* c2_Wr   = (const float*)d_in[12];
    const float* c2_br   = (const float*)d_in[13];
    const float* c2_We   = (const float*)d_in[14];
    const float* c2_att  = (const float*)d_in[15];
    const float* c2_bias = (const float*)d_in[16];
    const float* W1      = (const float*)d_in[17];
    const float* b1      = (const float*)d_in[18];
    const float* W2      = (const float*)d_in[19];
    const float* b2      = (const float*)d_in[20];
    const float* W3      = (const float*)d_in[21];
    const float* b3      = (const float*)d_in[22];
    float* out = (float*)d_out;

    float *p_xl, *p_xr, *p_h, *p_t1;
    int *p_eidx;
    cudaGetSymbolAddress((void**)&p_xl, g_xl);
    cudaGetSymbolAddress((void**)&p_xr, g_xr);
    cudaGetSymbolAddress((void**)&p_h, g_h);
    cudaGetSymbolAddress((void**)&p_t1, g_t1);
    cudaGetSymbolAddress((void**)&p_eidx, g_eidx);
    const int* src = p_eidx;
    const int* dst = p_eidx + E_EDGES;

    cudaFuncSetAttribute(edge_mma,
                         cudaFuncAttributeMaxDynamicSharedMemorySize, SM_TOTAL);

    int nsm = 148;
    cudaDeviceGetAttribute(&nsm, cudaDevAttrMultiProcessorCount, 0);

    const int T = 256;
    int gemm_blocks = (N_NODES + 127) / 128;
    int nhc_blocks = ((size_t)N_NODES * HC + T - 1) / T;

    detect_idx<<<1, 1>>>(ei_raw);
    conv_idx<<<(2 * E_EDGES + T - 1) / T, T>>>(ei_raw);

    pre_init<<<((size_t)N_NODES * LP + T - 1) / T, T>>>();
    loop_accum<<<(E_EDGES + T - 1) / T, T>>>(dst, ea);
    loop_fin<<<((size_t)N_NODES * EDIM + T - 1) / T, T>>>();

    // ---- layer 1 ----
    sgemm128x128<<<gemm_blocks, T>>>(x, c1_Wl, c1_bl, p_xl, N_NODES, 0);
    sgemm128x128<<<gemm_blocks, T>>>(x, c1_Wr, c1_br, p_xr, N_NODES, 0);
    layer_init<<<nhc_blocks, T>>>();
    edge_mma<<<nsm, 512, SM_TOTAL>>>(src, dst, ea, c1_We, c1_att);
    node_finalize<<<nhc_blocks, T>>>(c1_bias, p_h);

    // ---- layer 2 ----
    sgemm128x128<<<gemm_blocks, T>>>(p_h, c2_Wl, c2_bl, p_xl, N_NODES, 0);
    sgemm128x128<<<gemm_blocks, T>>>(p_h, c2_Wr, c2_br, p_xr, N_NODES, 0);
    layer_init<<<nhc_blocks, T>>>();
    edge_mma<<<nsm, 512, SM_TOTAL>>>(src, dst, ea, c2_We, c2_att);
    node_finalize<<<nhc_blocks, T>>>(c2_bias, p_h);

    // ---- MLP head ----
    sgemm128x128<<<gemm_blocks, T>>>(p_h, W1, b1, p_t1, N_NODES, 1);
    mlp_tail<<<(N_NODES + 15) / 16, 128>>>(W2, b2, W3, b3, out);
}

// round 10
// speedup vs baseline: 1.1310x; 1.1310x over previous
#include <cuda_runtime.h>
#include <cuda_bf16.h>
#include <math.h>
#include <stdint.h>

#define N_NODES 50000
#define E_EDGES 800000
#define N_ET    (E_EDGES + N_NODES)   // 850000 edges incl. self loops
#define EDIM    101
#define LP      104                   // padded loop_attr pitch
#define HC      128
#define NH      4

// ---- edge mma config: pair-local 16-edge blocks ----
#define NBLK    ((N_ET + 15) / 16)    // 53125 (divides exactly)
#define NKS     7                     // k-steps of 16 (K padded to 112)
#define PW      60                    // A/B row pitch in bf16x2 words
#define EEP     132                   // ee row pitch (floats)

// edge smem offsets (bytes)
#define SM_SS    0                    // 8 pairs * 16 int
#define SM_DS    512
#define SM_BHI   1024                 // 128*60*4 = 30720
#define SM_BLO   (SM_BHI + 30720)
#define SM_AHI   (SM_BLO + 30720)     // 8*16*60*4 = 30720
#define SM_ALO   (SM_AHI + 30720)
#define SM_EE    (SM_ALO + 30720)     // 8*16*132*4 = 67584
#define SM_TOTAL (SM_EE + 67584)      // 191488

// gemm smem (bytes): A/B hi+lo at pitch 68 words
#define GPW      68
#define GSM_BHI  0
#define GSM_BLO  (128*GPW*4)
#define GSM_AHI  (2*128*GPW*4)
#define GSM_ALO  (3*128*GPW*4)
#define GSM_TOTAL (4*128*GPW*4)       // 139264

// ------------------------------ scratch ------------------------------------
__device__ int      g_is64;
__device__ int      g_eidx[2 * E_EDGES];
__device__ float    g_loop[(size_t)N_NODES * LP];
__device__ float    g_cnt [N_NODES];
__device__ float    g_xl  [(size_t)N_NODES * HC];
__device__ float    g_xr  [(size_t)N_NODES * HC];
__device__ float    g_h   [(size_t)N_NODES * HC];
__device__ float    g_t1  [(size_t)N_NODES * HC];
__device__ float    g_den [(size_t)N_NODES * NH];
__device__ float    g_agg [(size_t)N_NODES * HC];
__device__ uint32_t g_bhi [128 * 64];   // preconverted weight (col-major words)
__device__ uint32_t g_blo [128 * 64];

// ------------------------------ helpers ------------------------------------
__device__ __forceinline__ void redAdd4(float* p, float4 v) {
    asm volatile("red.global.add.v4.f32 [%0], {%1,%2,%3,%4};"
                 :: "l"(p), "f"(v.x), "f"(v.y), "f"(v.z), "f"(v.w) : "memory");
}

// truncation-based bf16 hi/lo split of a float pair (residual 2^-16 after 3-term)
__device__ __forceinline__ void split_trunc(float v0, float v1,
                                            uint32_t& hi, uint32_t& lo) {
    uint32_t u0 = __float_as_uint(v0), u1 = __float_as_uint(v1);
    hi = __byte_perm(u0, u1, 0x7632);
    float r0 = v0 - __uint_as_float(u0 & 0xFFFF0000u);
    float r1 = v1 - __uint_as_float(u1 & 0xFFFF0000u);
    lo = __byte_perm(__float_as_uint(r0), __float_as_uint(r1), 0x7632);
}

// HMMA m16n8k16 bf16 (baseline PTX, sm_80+)
__device__ __forceinline__ void mma_bf16(float* d,
                                         uint32_t a0, uint32_t a1, uint32_t a2, uint32_t a3,
                                         uint32_t b0, uint32_t b1) {
    asm volatile("mma.sync.aligned.m16n8k16.row.col.f32.bf16.bf16.f32 "
                 "{%0,%1,%2,%3}, {%4,%5,%6,%7}, {%8,%9}, {%0,%1,%2,%3};"
                 : "+f"(d[0]), "+f"(d[1]), "+f"(d[2]), "+f"(d[3])
                 : "r"(a0), "r"(a1), "r"(a2), "r"(a3), "r"(b0), "r"(b1));
}

#define PAIR_BAR(pair) asm volatile("bar.sync %0, %1;" :: "r"((pair) + 1), "r"(64) : "memory")

// ------------------------------ index dtype hedge ---------------------------
__global__ void detect_idx(const void* ei) {
    const int* p = (const int*)ei;
    int all0 = 1;
    for (int i = 1; i < 64; i += 2) if (p[i] != 0) all0 = 0;
    g_is64 = all0;
}

__global__ void conv_idx(const void* ei) {
    int i = blockIdx.x * blockDim.x + threadIdx.x;
    if (i >= 2 * E_EDGES) return;
    int v;
    if (g_is64) v = (int)((const long long*)ei)[i];
    else        v = ((const int*)ei)[i];
    g_eidx[i] = v;
}

// ------------------------------ self-loop attr -----------------------------
__global__ void pre_init() {
    size_t i = (size_t)blockIdx.x * blockDim.x + threadIdx.x;
    if (i < (size_t)N_NODES * LP) g_loop[i] = 0.f;
    if (i < N_NODES) g_cnt[i] = 0.f;
}

__global__ void loop_accum(const int* __restrict__ dst, const float* __restrict__ ea) {
    int e = blockIdx.x * blockDim.x + threadIdx.x;
    if (e >= E_EDGES) return;
    int d = dst[e];
    float* out = g_loop + (size_t)d * LP;
    const float* a = ea + (size_t)e * EDIM;
#pragma unroll
    for (int k = 0; k < 100; k += 4) {
        float4 v = make_float4(a[k], a[k+1], a[k+2], a[k+3]);
        redAdd4(out + k, v);
    }
    atomicAdd(out + 100, a[100]);
    atomicAdd(&g_cnt[d], 1.0f);
}

__global__ void loop_fin() {
    size_t i = (size_t)blockIdx.x * blockDim.x + threadIdx.x;
    if (i >= (size_t)N_NODES * EDIM) return;
    int n = (int)(i / EDIM);
    int k = (int)(i - (size_t)n * EDIM);
    g_loop[(size_t)n * LP + k] *= 1.f / fmaxf(g_cnt[n], 1.f);
}

// ---------------- weight preconversion: W[k][c] -> colmajor hi/lo words -----
__global__ void convW(const float* __restrict__ W, int kmax) {
    int idx = blockIdx.x * 256 + threadIdx.x;
    if (idx >= 128 * 64) return;
    int c = idx >> 6, kq = idx & 63;
    int k = kq * 2;
    float v0 = (k     < kmax) ? W[(size_t)k * 128 + c]       : 0.f;
    float v1 = (k + 1 < kmax) ? W[(size_t)(k + 1) * 128 + c] : 0.f;
    uint32_t h, l;
    split_trunc(v0, v1, h, l);
    g_bhi[idx] = h;
    g_blo[idx] = l;
}

// ------------- HMMA node GEMM: C = [relu](A[M,128] @ W + bias) --------------
// W preconverted in g_bhi/g_blo. 512 threads, 128 rows per block.
__global__ __launch_bounds__(512, 1)
void gemm_mma(const float* __restrict__ A, const float* __restrict__ bias,
              float* __restrict__ C, int M, int relu) {
    extern __shared__ __align__(16) char sm[];
    uint32_t* Bh = (uint32_t*)(sm + GSM_BHI);
    uint32_t* Bl = (uint32_t*)(sm + GSM_BLO);
    uint32_t* Ah = (uint32_t*)(sm + GSM_AHI);
    uint32_t* Al = (uint32_t*)(sm + GSM_ALO);

    int t = threadIdx.x;
    int lane = t & 31;
    int w = t >> 5;
    int mb = w >> 1, half = w & 1;
    int r0 = lane >> 2, kp = lane & 3;
    int m0 = blockIdx.x << 7;

    // copy preconverted W into padded smem
#pragma unroll
    for (int i = 0; i < 16; i++) {
        int idx = t + i * 512;
        int c = idx >> 6, kq = idx & 63;
        Bh[c * GPW + kq] = g_bhi[idx];
        Bl[c * GPW + kq] = g_blo[idx];
    }
    // stage A rows (convert fp32 -> hi/lo)
    {
        int r = t >> 2;
        int kq0 = (t & 3) << 4;       // 16 words = 32 floats
        int m = m0 + r;
        const float* ap = A + (size_t)m * 128 + (kq0 << 1);
        uint32_t* ah = Ah + r * GPW + kq0;
        uint32_t* al = Al + r * GPW + kq0;
        bool ok = (m < M);
#pragma unroll
        for (int i = 0; i < 16; i++) {
            float v0 = ok ? ap[2*i]     : 0.f;
            float v1 = ok ? ap[2*i + 1] : 0.f;
            uint32_t h, l;
            split_trunc(v0, v1, h, l);
            ah[i] = h;
            al[i] = l;
        }
    }
    __syncthreads();

    float acc[8][4];
#pragma unroll
    for (int nb = 0; nb < 8; nb++)
#pragma unroll
        for (int j = 0; j < 4; j++) acc[nb][j] = 0.f;

    const uint32_t* Awh = Ah + (mb << 4) * GPW;
    const uint32_t* Awl = Al + (mb << 4) * GPW;
    const uint32_t* Bwh = Bh + (half << 6) * GPW;
    const uint32_t* Bwl = Bl + (half << 6) * GPW;

#pragma unroll
    for (int ks = 0; ks < 8; ks++) {
        int abase = r0 * GPW + ks * 8 + kp;
        uint32_t ah0 = Awh[abase],     ah1 = Awh[abase + 8 * GPW];
        uint32_t ah2 = Awh[abase + 4], ah3 = Awh[abase + 8 * GPW + 4];
        uint32_t al0 = Awl[abase],     al1 = Awl[abase + 8 * GPW];
        uint32_t al2 = Awl[abase + 4], al3 = Awl[abase + 8 * GPW + 4];
#pragma unroll
        for (int nb = 0; nb < 8; nb++) {
            int bbase = ((nb << 3) + r0) * GPW + ks * 8 + kp;
            uint32_t bh0 = Bwh[bbase], bh1 = Bwh[bbase + 4];
            uint32_t bl0 = Bwl[bbase], bl1 = Bwl[bbase + 4];
            mma_bf16(acc[nb], ah0, ah1, ah2, ah3, bh0, bh1);
            mma_bf16(acc[nb], ah0, ah1, ah2, ah3, bl0, bl1);
            mma_bf16(acc[nb], al0, al1, al2, al3, bh0, bh1);
        }
    }

    // epilogue: bias + relu + store
    int cb = (half << 6) + (kp << 1);
    int mA = m0 + (mb << 4) + r0;
    int mB = mA + 8;
#pragma unroll
    for (int nb = 0; nb < 8; nb++) {
        int c0 = cb + (nb << 3);
        float2 bv = *(const float2*)(bias + c0);
        float o0 = acc[nb][0] + bv.x, o1 = acc[nb][1] + bv.y;
        float o2 = acc[nb][2] + bv.x, o3 = acc[nb][3] + bv.y;
        if (relu) {
            o0 = fmaxf(o0, 0.f); o1 = fmaxf(o1, 0.f);
            o2 = fmaxf(o2, 0.f); o3 = fmaxf(o3, 0.f);
        }
        if (mA < M) *(float2*)(C + (size_t)mA * 128 + c0) = make_float2(o0, o1);
        if (mB < M) *(float2*)(C + (size_t)mB * 128 + c0) = make_float2(o2, o3);
    }
}

// ------------------------------ per-layer init ------------------------------
__global__ void layer_init() {
    size_t i = (size_t)blockIdx.x * blockDim.x + threadIdx.x;
    if (i < (size_t)N_NODES * HC) g_agg[i] = 0.f;
    if (i < (size_t)N_NODES * NH) g_den[i] = 0.f;
}

// ==== HMMA fused edge kernel, PAIR-LOCAL pipelines ==========================
// 512 threads = 8 warp-pairs. Pair p: independent stream of 16-edge blocks,
// own A/ee/idx smem slices, named barrier (p+1, 64). We preconverted in g_bhi.
__device__ __forceinline__ void prefetch_attrs(size_t e, int kbase, float* pf,
                                               const float* __restrict__ eattr) {
    bool ok = (e < (size_t)N_ET);
    const float* bp = (e < E_EDGES) ? (eattr + e * EDIM)
                    : (g_loop + (ok ? (e - E_EDGES) : 0) * (size_t)LP);
#pragma unroll
    for (int i = 0; i < 28; i++) {
        int k = kbase + i;
        pf[i] = (ok && k < EDIM) ? bp[k] : 0.f;
    }
}

__global__ __launch_bounds__(512, 1)
void edge_mma(const int* __restrict__ src, const int* __restrict__ dst,
              const float* __restrict__ eattr, const float* __restrict__ att) {
    extern __shared__ __align__(16) char sm[];
    int*      ssS = (int*)(sm + SM_SS);
    int*      dsS = (int*)(sm + SM_DS);
    uint32_t* Bhi = (uint32_t*)(sm + SM_BHI);
    uint32_t* Blo = (uint32_t*)(sm + SM_BLO);
    uint32_t* Ahi = (uint32_t*)(sm + SM_AHI);
    uint32_t* Alo = (uint32_t*)(sm + SM_ALO);
    float*    ee  = (float*)(sm + SM_EE);

    int t = threadIdx.x;
    int lane = t & 31;
    int w = t >> 5;
    int pair = w >> 1, half = w & 1;
    int r0 = lane >> 2, kp = lane & 3;
    int head = lane >> 3;
    int u = t & 63;                    // pair-local tid

    // copy preconverted We into padded smem (words 0..55 used)
#pragma unroll
    for (int i = 0; i < 16; i++) {
        int idx = t + i * 512;
        int kq = idx & 63;
        if (kq < 56) {
            int c = idx >> 6;
            Bhi[c * PW + kq] = g_bhi[idx];
            Blo[c * PW + kq] = g_blo[idx];
        }
    }
    float4 av = *(const float4*)(att + (lane << 2));
    __syncthreads();

    uint32_t* pAh = Ahi + pair * (16 * PW);
    uint32_t* pAl = Alo + pair * (16 * PW);
    float*    pee = ee  + pair * (16 * EEP);
    float2*   pee2 = (float2*)pee;
    int*      pss = ssS + (pair << 4);
    int*      pds = dsS + (pair << 4);

    const uint32_t* Bwh = Bhi + (half << 6) * PW;
    const uint32_t* Bwl = Blo + (half << 6) * PW;

    int e_st = u >> 2;                 // local edge 0..15 staged by this thread
    int kq0 = (u & 3) * 14;
    int kbase = kq0 * 2;
    int stride = gridDim.x * 8;
    int blk0 = blockIdx.x * 8 + pair;

    float pf[28];
    prefetch_attrs((size_t)blk0 * 16 + e_st, kbase, pf, eattr);

    for (int blk = blk0; blk < NBLK; blk += stride) {
        size_t e0 = (size_t)blk * 16;

        // stage indices (pair-local)
        if (u < 16) {
            size_t e = e0 + u;
            int s = 0, d = 0;
            if (e < (size_t)N_ET) {
                if (e < E_EDGES) { s = src[e]; d = dst[e]; }
                else             { s = d = (int)(e - E_EDGES); }
            }
            pss[u] = s; pds[u] = d;
        }
        // convert prefetched attrs -> A hi/lo
        {
            uint32_t* ah = pAh + e_st * PW;
            uint32_t* al = pAl + e_st * PW;
#pragma unroll
            for (int i = 0; i < 14; i++) {
                uint32_t h, l;
                split_trunc(pf[2*i], pf[2*i + 1], h, l);
                ah[kq0 + i] = h;
                al[kq0 + i] = l;
            }
        }
        // prefetch next block
        if (blk + stride < NBLK)
            prefetch_attrs((size_t)(blk + stride) * 16 + e_st, kbase, pf, eattr);

        PAIR_BAR(pair);               // A, indices visible to pair

        // ---- HMMA: D = Ahi*Bhi + Ahi*Blo + Alo*Bhi ----
        float acc[8][4];
#pragma unroll
        for (int nb = 0; nb < 8; nb++)
#pragma unroll
            for (int j = 0; j < 4; j++) acc[nb][j] = 0.f;

#pragma unroll
        for (int ks = 0; ks < NKS; ks++) {
            int abase = r0 * PW + ks * 8 + kp;
            uint32_t ah0 = pAh[abase],     ah1 = pAh[abase + 8 * PW];
            uint32_t ah2 = pAh[abase + 4], ah3 = pAh[abase + 8 * PW + 4];
            uint32_t al0 = pAl[abase],     al1 = pAl[abase + 8 * PW];
            uint32_t al2 = pAl[abase + 4], al3 = pAl[abase + 8 * PW + 4];
#pragma unroll
            for (int nb = 0; nb < 8; nb++) {
                int bbase = ((nb << 3) + r0) * PW + ks * 8 + kp;
                uint32_t bh0 = Bwh[bbase], bh1 = Bwh[bbase + 4];
                uint32_t bl0 = Bwl[bbase], bl1 = Bwl[bbase + 4];
                mma_bf16(acc[nb], ah0, ah1, ah2, ah3, bh0, bh1);
                mma_bf16(acc[nb], ah0, ah1, ah2, ah3, bl0, bl1);
                mma_bf16(acc[nb], al0, al1, al2, al3, bh0, bh1);
            }
        }

        // store D fragments to pair-local ee
#pragma unroll
        for (int nb = 0; nb < 8; nb++) {
            int col2 = (half << 5) + (nb << 2) + kp;  // float2 units
            pee2[r0 * (EEP / 2) + col2]       = make_float2(acc[nb][0], acc[nb][1]);
            pee2[(r0 + 8) * (EEP / 2) + col2] = make_float2(acc[nb][2], acc[nb][3]);
        }

        // snapshot indices for epilogue BEFORE bar (next stage overwrites pss)
        int sreg[8], dreg[8];
        bool vv[8];
#pragma unroll
        for (int i = 0; i < 8; i++) {
            int el = (half << 3) + i;
            size_t e = e0 + el;
            vv[i] = (e < (size_t)N_ET);
            sreg[i] = vv[i] ? pss[el] : 0;
            dreg[i] = vv[i] ? pds[el] : 0;
        }

        PAIR_BAR(pair);               // ee complete (both halves)

        // ---- epilogue: 8 edges, 2 batches of 4 (gathers overlap) ----
#pragma unroll
        for (int g = 0; g < 2; g++) {
            float4 xlv[4], xrv[4];
#pragma unroll
            for (int i = 0; i < 4; i++) {
                int j = (g << 2) + i;
                xlv[i] = *(const float4*)(g_xl + (size_t)sreg[j] * HC + (lane << 2));
                xrv[i] = *(const float4*)(g_xr + (size_t)dreg[j] * HC + (lane << 2));
            }
#pragma unroll
            for (int i = 0; i < 4; i++) {
                int j = (g << 2) + i;
                int el = (half << 3) + j;
                float4 eev = *(const float4*)(pee + el * EEP + (lane << 2));
                float z0 = eev.x + xlv[i].x + xrv[i].x;
                float z1 = eev.y + xlv[i].y + xrv[i].y;
                float z2 = eev.z + xlv[i].z + xrv[i].z;
                float z3 = eev.w + xlv[i].w + xrv[i].w;
                z0 = (z0 > 0.f) ? z0 : 0.2f * z0;
                z1 = (z1 > 0.f) ? z1 : 0.2f * z1;
                z2 = (z2 > 0.f) ? z2 : 0.2f * z2;
                z3 = (z3 > 0.f) ? z3 : 0.2f * z3;
                float part = z0 * av.x + z1 * av.y + z2 * av.z + z3 * av.w;
                part += __shfl_xor_sync(0xffffffffu, part, 1);
                part += __shfl_xor_sync(0xffffffffu, part, 2);
                part += __shfl_xor_sync(0xffffffffu, part, 4);
                float ex = __expf(part);
                if (vv[j]) {
                    if ((lane & 7) == 0)
                        atomicAdd(&g_den[(size_t)dreg[j] * NH + head], ex);
                    redAdd4(g_agg + (size_t)dreg[j] * HC + (lane << 2),
                            make_float4(ex * xlv[i].x, ex * xlv[i].y,
                                        ex * xlv[i].z, ex * xlv[i].w));
                }
            }
        }
    }
}

// --------------------- h = relu(agg/(den+eps) + bias) ----------------------
__global__ void node_finalize(const float* __restrict__ bias, float* __restrict__ out) {
    size_t i = (size_t)blockIdx.x * blockDim.x + threadIdx.x;
    if (i >= (size_t)N_NODES * HC) return;
    int n = (int)(i >> 7), c = (int)(i & 127);
    float den = g_den[(size_t)n * NH + (c >> 5)];
    float v = g_agg[i] / (den + 1e-16f) + bias[c];
    out[i] = fmaxf(v, 0.f);
}

// --------------------- MLP tail: relu(t1@W2+b2) @ W3 + b3 ------------------
__global__ void mlp_tail(const float* __restrict__ W2, const float* __restrict__ b2,
                         const float* __restrict__ W3, const float* __restrict__ b3,
                         float* __restrict__ out) {
    __shared__ float W2s[128 * 64];
    __shared__ float t1s[16 * 132];
    __shared__ float W3s[64];
    int t = threadIdx.x;
    int n0 = blockIdx.x * 16;
    for (int i = t; i < 128 * 64 / 4; i += 128)
        ((float4*)W2s)[i] = ((const float4*)W2)[i];
    if (t < 64) W3s[t] = W3[t];
    for (int i = t; i < 16 * 128; i += 128) {
        int ln = i >> 7, k = i & 127;
        int n = n0 + ln;
        t1s[ln * 132 + k] = (n < N_NODES) ? g_t1[(size_t)n * 128 + k] : 0.f;
    }
    __syncthreads();
    int ln = t >> 3, jg = t & 7;
    float acc[8] = {0.f, 0.f, 0.f, 0.f, 0.f, 0.f, 0.f, 0.f};
#pragma unroll 4
    for (int k = 0; k < 128; k++) {
        float a = t1s[ln * 132 + k];
        float4 w0 = *(const float4*)(W2s + k * 64 + jg * 8);
        float4 w1 = *(const float4*)(W2s + k * 64 + jg * 8 + 4);
        acc[0] += a * w0.x; acc[1] += a * w0.y; acc[2] += a * w0.z; acc[3] += a * w0.w;
        acc[4] += a * w1.x; acc[5] += a * w1.y; acc[6] += a * w1.z; acc[7] += a * w1.w;
    }
    float part = 0.f;
#pragma unroll
    for (int j = 0; j < 8; j++) {
        float t2 = fmaxf(acc[j] + b2[jg * 8 + j], 0.f);
        part += t2 * W3s[jg * 8 + j];
    }
    part += __shfl_down_sync(0xffffffffu, part, 4, 8);
    part += __shfl_down_sync(0xffffffffu, part, 2, 8);
    part += __shfl_down_sync(0xffffffffu, part, 1, 8);
    int n = n0 + ln;
    if (jg == 0 && n < N_NODES) out[n] = part + b3[0];
}

// ------------------------------ launch -------------------------------------
extern "C" void kernel_launch(void* const* d_in, const int* in_sizes, int n_in,
                              void* d_out, int out_size) {
    const float* x       = (const float*)d_in[0];
    const void*  ei_raw  = d_in[1];
    const float* ea      = (const float*)d_in[2];
    const float* c1_Wl   = (const float*)d_in[3];
    const float* c1_bl   = (const float*)d_in[4];
    const float* c1_Wr   = (const float*)d_in[5];
    const float* c1_br   = (const float*)d_in[6];
    const float* c1_We   = (const float*)d_in[7];
    const float* c1_att  = (const float*)d_in[8];
    const float* c1_bias = (const float*)d_in[9];
    const float* c2_Wl   = (const float*)d_in[10];
    const float* c2_bl   = (const float*)d_in[11];
    const float* c2_Wr   = (const float*)d_in[12];
    const float* c2_br   = (const float*)d_in[13];
    const float* c2_We   = (const float*)d_in[14];
    const float* c2_att  = (const float*)d_in[15];
    const float* c2_bias = (const float*)d_in[16];
    const float* W1      = (const float*)d_in[17];
    const float* b1      = (const float*)d_in[18];
    const float* W2      = (const float*)d_in[19];
    const float* b2      = (const float*)d_in[20];
    const float* W3      = (const float*)d_in[21];
    const float* b3      = (const float*)d_in[22];
    float* out = (float*)d_out;

    float *p_xl, *p_xr, *p_h, *p_t1;
    int *p_eidx;
    cudaGetSymbolAddress((void**)&p_xl, g_xl);
    cudaGetSymbolAddress((void**)&p_xr, g_xr);
    cudaGetSymbolAddress((void**)&p_h, g_h);
    cudaGetSymbolAddress((void**)&p_t1, g_t1);
    cudaGetSymbolAddress((void**)&p_eidx, g_eidx);
    const int* src = p_eidx;
    const int* dst = p_eidx + E_EDGES;

    cudaFuncSetAttribute(edge_mma,
                         cudaFuncAttributeMaxDynamicSharedMemorySize, SM_TOTAL);
    cudaFuncSetAttribute(gemm_mma,
                         cudaFuncAttributeMaxDynamicSharedMemorySize, GSM_TOTAL);

    int nsm = 148;
    cudaDeviceGetAttribute(&nsm, cudaDevAttrMultiProcessorCount, 0);

    const int T = 256;
    int gemm_blocks = (N_NODES + 127) / 128;   // 391
    int nhc_blocks = ((size_t)N_NODES * HC + T - 1) / T;
    int cw_blocks = (128 * 64 + 255) / 256;    // 32

    detect_idx<<<1, 1>>>(ei_raw);
    conv_idx<<<(2 * E_EDGES + T - 1) / T, T>>>(ei_raw);

    pre_init<<<((size_t)N_NODES * LP + T - 1) / T, T>>>();
    loop_accum<<<(E_EDGES + T - 1) / T, T>>>(dst, ea);
    loop_fin<<<((size_t)N_NODES * EDIM + T - 1) / T, T>>>();

    // ---- layer 1 ----
    convW<<<cw_blocks, 256>>>(c1_Wl, 128);
    gemm_mma<<<gemm_blocks, 512, GSM_TOTAL>>>(x, c1_bl, p_xl, N_NODES, 0);
    convW<<<cw_blocks, 256>>>(c1_Wr, 128);
    gemm_mma<<<gemm_blocks, 512, GSM_TOTAL>>>(x, c1_br, p_xr, N_NODES, 0);
    layer_init<<<nhc_blocks, T>>>();
    convW<<<cw_blocks, 256>>>(c1_We, EDIM);
    edge_mma<<<nsm, 512, SM_TOTAL>>>(src, dst, ea, c1_att);
    node_finalize<<<nhc_blocks, T>>>(c1_bias, p_h);

    // ---- layer 2 ----
    convW<<<cw_blocks, 256>>>(c2_Wl, 128);
    gemm_mma<<<gemm_blocks, 512, GSM_TOTAL>>>(p_h, c2_bl, p_xl, N_NODES, 0);
    convW<<<cw_blocks, 256>>>(c2_Wr, 128);
    gemm_mma<<<gemm_blocks, 512, GSM_TOTAL>>>(p_h, c2_br, p_xr, N_NODES, 0);
    layer_init<<<nhc_blocks, T>>>();
    convW<<<cw_blocks, 256>>>(c2_We, EDIM);
    edge_mma<<<nsm, 512, SM_TOTAL>>>(src, dst, ea, c2_att);
    node_finalize<<<nhc_blocks, T>>>(c2_bias, p_h);

    // ---- MLP head ----
    convW<<<cw_blocks, 256>>>(W1, 128);
    gemm_mma<<<gemm_blocks, 512, GSM_TOTAL>>>(p_h, b1, p_t1, N_NODES, 1);
    mlp_tail<<<(N_NODES + 15) / 16, 128>>>(W2, b2, W3, b3, out);
}